// round 3
// baseline (speedup 1.0000x reference)
#include <cuda_runtime.h>

// ---------------- problem constants ----------------
#define D_MODEL  1024
#define D_STATE  16
#define D_CONV   4
#define D_INNER  2048
#define BATCH    2
#define SEQ      2048
#define ROWS     (BATCH*SEQ)          // 4096

// ---------------- scratch (static __device__, no allocs) ----------------
__device__ float g_xz  [ROWS * 2 * D_INNER];   // [4096, 4096]  x_proj | z
__device__ float g_xact[ROWS * D_INNER];       // conv+silu output
__device__ float g_dt  [ROWS * D_INNER];       // softplus(dt)
__device__ float g_yg  [ROWS * D_INNER];       // gated ssm output

// ---------------- f32x2 helpers (Blackwell packed fp32) ----------------
__device__ __forceinline__ unsigned long long pack2(float lo, float hi) {
    unsigned long long r;
    asm("mov.b64 %0, {%1,%2};" : "=l"(r) : "f"(lo), "f"(hi));
    return r;
}
__device__ __forceinline__ float2 unpack2(unsigned long long v) {
    float2 r;
    asm("mov.b64 {%0,%1}, %2;" : "=f"(r.x), "=f"(r.y) : "l"(v));
    return r;
}
__device__ __forceinline__ void ffma2(unsigned long long& d,
                                      unsigned long long a,
                                      unsigned long long b) {
    asm("fma.rn.f32x2 %0, %1, %2, %0;" : "+l"(d) : "l"(a), "l"(b));
}

__device__ __forceinline__ float softplus_f(float v) {
    return fmaxf(v, 0.0f) + log1pf(__expf(-fabsf(v)));
}

// ---------------- GEMM: C[M,N] = A[M,K] * B[N,K]^T  (both row-major) ----------------
// 128x128 block tile, BK=16, 256 threads, 8x8 per-thread tile, f32x2 FMAs.
// epi = 0: plain store;  epi = 1: softplus(v + bias[n])
__global__ void __launch_bounds__(256)
gemm_tn(const float* __restrict__ A, const float* __restrict__ B,
        float* __restrict__ C, int M, int N, int K,
        const float* __restrict__ bias, int epi)
{
    __shared__ __align__(16) float As[16][128];
    __shared__ __align__(16) float Bs[16][128];

    const int tid = threadIdx.x;
    const int m0  = blockIdx.y * 128;
    const int n0  = blockIdx.x * 128;
    const int tx  = tid & 15;          // 0..15 -> col group
    const int ty  = tid >> 4;          // 0..15 -> row group
    const int r0  = ty * 8;
    const int c0  = tx * 8;

    // global-load mapping: 512 float4 per tile, 2 per thread
    const int q0r = tid >> 2;          // row within tile for f4 #0 (0..63)
    const int q0c = tid & 3;           // which float4 within the 16-wide row
    const int q1r = q0r + 64;          // row for f4 #1

    unsigned long long acc[8][4];
#pragma unroll
    for (int i = 0; i < 8; i++)
#pragma unroll
        for (int j = 0; j < 4; j++) acc[i][j] = 0ULL;

    const int ktiles = K >> 4;
    for (int kt = 0; kt < ktiles; kt++) {
        const int kbase = kt * 16;
        // load A and B tiles (transposed into As[k][m] / Bs[k][n])
        float4 v0 = *(const float4*)(A + (size_t)(m0 + q0r) * K + kbase + q0c * 4);
        float4 v1 = *(const float4*)(A + (size_t)(m0 + q1r) * K + kbase + q0c * 4);
        float4 w0 = *(const float4*)(B + (size_t)(n0 + q0r) * K + kbase + q0c * 4);
        float4 w1 = *(const float4*)(B + (size_t)(n0 + q1r) * K + kbase + q0c * 4);

        As[q0c * 4 + 0][q0r] = v0.x; As[q0c * 4 + 1][q0r] = v0.y;
        As[q0c * 4 + 2][q0r] = v0.z; As[q0c * 4 + 3][q0r] = v0.w;
        As[q0c * 4 + 0][q1r] = v1.x; As[q0c * 4 + 1][q1r] = v1.y;
        As[q0c * 4 + 2][q1r] = v1.z; As[q0c * 4 + 3][q1r] = v1.w;
        Bs[q0c * 4 + 0][q0r] = w0.x; Bs[q0c * 4 + 1][q0r] = w0.y;
        Bs[q0c * 4 + 2][q0r] = w0.z; Bs[q0c * 4 + 3][q0r] = w0.w;
        Bs[q0c * 4 + 0][q1r] = w1.x; Bs[q0c * 4 + 1][q1r] = w1.y;
        Bs[q0c * 4 + 2][q1r] = w1.z; Bs[q0c * 4 + 3][q1r] = w1.w;
        __syncthreads();

#pragma unroll
        for (int k = 0; k < 16; k++) {
            float a[8];
            *(float4*)&a[0] = *(const float4*)&As[k][r0];
            *(float4*)&a[4] = *(const float4*)&As[k][r0 + 4];
            unsigned long long b2[4];
            {
                ulonglong2 t0 = *(const ulonglong2*)&Bs[k][c0];
                ulonglong2 t1 = *(const ulonglong2*)&Bs[k][c0 + 4];
                b2[0] = t0.x; b2[1] = t0.y; b2[2] = t1.x; b2[3] = t1.y;
            }
#pragma unroll
            for (int i = 0; i < 8; i++) {
                unsigned long long aa = pack2(a[i], a[i]);
#pragma unroll
                for (int j = 0; j < 4; j++) ffma2(acc[i][j], aa, b2[j]);
            }
        }
        __syncthreads();
    }

    // epilogue
#pragma unroll
    for (int i = 0; i < 8; i++) {
        const int m = m0 + r0 + i;
#pragma unroll
        for (int j = 0; j < 4; j++) {
            const int n = n0 + c0 + 2 * j;
            float2 v = unpack2(acc[i][j]);
            if (epi == 1) {
                v.x = softplus_f(v.x + bias[n]);
                v.y = softplus_f(v.y + bias[n + 1]);
            }
            *(float2*)(C + (size_t)m * N + n) = v;
        }
    }
}

// ---------------- depthwise causal conv1d + SiLU ----------------
__global__ void conv_silu_kernel(const float* __restrict__ conv_w,
                                 const float* __restrict__ conv_b)
{
    int idx = blockIdx.x * blockDim.x + threadIdx.x;    // over ROWS*D_INNER
    if (idx >= ROWS * D_INNER) return;
    int d   = idx & (D_INNER - 1);
    int row = idx >> 11;                 // / D_INNER
    int t   = row & (SEQ - 1);
    int b   = row >> 11;                 // / SEQ

    float acc = conv_b[d];
#pragma unroll
    for (int j = 0; j < D_CONV; j++) {
        int tt = t - (D_CONV - 1) + j;
        if (tt >= 0)
            acc = fmaf(conv_w[d * D_CONV + j],
                       g_xz[(size_t)(b * SEQ + tt) * (2 * D_INNER) + d], acc);
    }
    float sig = 1.0f / (1.0f + __expf(-acc));
    g_xact[idx] = acc * sig;
}

// ---------------- selective scan + gating ----------------
// one thread per (b, d, s): 65536 threads; lanes [16k..16k+15] share a channel
__global__ void __launch_bounds__(256)
scan_kernel(const float* __restrict__ A_log, const float* __restrict__ Dp)
{
    int g   = blockIdx.x * blockDim.x + threadIdx.x;
    int s   = g & (D_STATE - 1);
    int dch = g >> 4;                    // b*D_INNER + d
    int b   = dch >> 11;                 // / D_INNER
    int d   = dch & (D_INNER - 1);

    const float a   = -__expf(A_log[d * D_STATE + s]);
    const float dpv = Dp[d];

    const float* dt_ptr = g_dt   + (size_t)(b * SEQ) * D_INNER + d;
    const float* x_ptr  = g_xact + (size_t)(b * SEQ) * D_INNER + d;
    const float* z_ptr  = g_xz   + (size_t)(b * SEQ) * (2 * D_INNER) + D_INNER + d;
    float*       y_ptr  = g_yg   + (size_t)(b * SEQ) * D_INNER + d;

    float h = 0.0f;
#pragma unroll 4
    for (int t = 0; t < SEQ; t++) {
        float dtv = dt_ptr[(size_t)t * D_INNER];
        float xv  = x_ptr [(size_t)t * D_INNER];
        float e   = __expf(dtv * a);
        h = fmaf(e, h, dtv * xv);

        float y = h;
        y += __shfl_xor_sync(0xffffffffu, y, 1);
        y += __shfl_xor_sync(0xffffffffu, y, 2);
        y += __shfl_xor_sync(0xffffffffu, y, 4);
        y += __shfl_xor_sync(0xffffffffu, y, 8);

        if (s == 0) {
            float zv  = z_ptr[(size_t)t * (2 * D_INNER)];
            float sig = 1.0f / (1.0f + __expf(-zv));
            y_ptr[(size_t)t * D_INNER] = (y + dpv * xv) * (zv * sig);
        }
    }
}

// ---------------- launch ----------------
extern "C" void kernel_launch(void* const* d_in, const int* in_sizes, int n_in,
                              void* d_out, int out_size)
{
    const float* x      = (const float*)d_in[0];
    const float* W_in   = (const float*)d_in[1];
    const float* conv_w = (const float*)d_in[2];
    const float* conv_b = (const float*)d_in[3];
    const float* A_log  = (const float*)d_in[4];
    const float* Dp     = (const float*)d_in[5];
    const float* W_dt   = (const float*)d_in[6];
    const float* b_dt   = (const float*)d_in[7];
    const float* W_out  = (const float*)d_in[8];
    float* out = (float*)d_out;

    float *p_xz, *p_xact, *p_dt, *p_yg;
    cudaGetSymbolAddress((void**)&p_xz,   g_xz);
    cudaGetSymbolAddress((void**)&p_xact, g_xact);
    cudaGetSymbolAddress((void**)&p_dt,   g_dt);
    cudaGetSymbolAddress((void**)&p_yg,   g_yg);

    // G1: xz = x @ W_in^T    [4096,1024] x [4096,1024]^T -> [4096,4096]
    gemm_tn<<<dim3((2 * D_INNER) / 128, ROWS / 128), 256>>>(
        x, W_in, p_xz, ROWS, 2 * D_INNER, D_MODEL, nullptr, 0);

    // conv + silu -> g_xact
    conv_silu_kernel<<<(ROWS * D_INNER) / 256, 256>>>(conv_w, conv_b);

    // G2: dt = softplus(x_act @ W_dt^T + b_dt)  [4096,2048]x[2048,2048]^T
    gemm_tn<<<dim3(D_INNER / 128, ROWS / 128), 256>>>(
        p_xact, W_dt, p_dt, ROWS, D_INNER, D_INNER, b_dt, 1);

    // scan + gating -> g_yg   (BATCH*D_INNER*D_STATE = 65536 threads)
    scan_kernel<<<(BATCH * D_INNER * D_STATE) / 256, 256>>>(A_log, Dp);

    // G3: out = y_gated @ W_out^T -> d_out [4096, 1024]
    gemm_tn<<<dim3(D_MODEL / 128, ROWS / 128), 256>>>(
        p_yg, W_out, out, ROWS, D_MODEL, D_INNER, nullptr, 0);
}